// round 10
// baseline (speedup 1.0000x reference)
#include <cuda_runtime.h>

#define BQ    4
#define NQ    8192
#define G     32
#define NC    (G * G * G)          // 32768 cells per batch
#define GRID_MIN (-3.0f)
#define CELL     (6.0f / G)        // 0.1875
#define INV_CELL (G / 6.0f)

// ---- scratch (__device__ globals; no allocation) ----
__device__ int   g_cnt_r[BQ * NC];
__device__ int   g_cnt_q[BQ * NC];
__device__ int   g_start_r[BQ * (NC + 1)];
__device__ int   g_start_q[BQ * (NC + 1)];
__device__ int   g_cur_r[BQ * NC];
__device__ int   g_cur_q[BQ * NC];
__device__ float g_rx[BQ * NQ], g_ry[BQ * NQ], g_rz[BQ * NQ];  // cell-sorted refs
__device__ float g_qx[BQ * NQ], g_qy[BQ * NQ], g_qz[BQ * NQ];  // cell-sorted queries
__device__ int   g_qid[BQ * NQ];                                // original query index
__device__ float g_nn[BQ * NQ];                                 // nn sq dist @ ORIGINAL index
__device__ float g_part[128];

__device__ __forceinline__ int clampi(int v, int lo, int hi) {
    return v < lo ? lo : (v > hi ? hi : v);
}
__device__ __forceinline__ void cell_coords(float x, float y, float z,
                                            int& cx, int& cy, int& cz) {
    cx = clampi((int)floorf((x - GRID_MIN) * INV_CELL), 0, G - 1);
    cy = clampi((int)floorf((y - GRID_MIN) * INV_CELL), 0, G - 1);
    cz = clampi((int)floorf((z - GRID_MIN) * INV_CELL), 0, G - 1);
}

// 1) zero both count arrays
__global__ void k_zero() {
    int i = blockIdx.x * blockDim.x + threadIdx.x;
    if (i < BQ * NC) { g_cnt_r[i] = 0; g_cnt_q[i] = 0; }
}

// 2) count points per cell (refs then queries)
__global__ void k_count(const float* __restrict__ pc2,
                        const float* __restrict__ pc1w) {
    int t = blockIdx.x * blockDim.x + threadIdx.x;
    if (t >= 2 * BQ * NQ) return;
    int isq = t >= BQ * NQ;                 // 0 = ref, 1 = query
    int p = isq ? t - BQ * NQ : t;
    int b = p / NQ, i = p - b * NQ;
    const float* src = isq ? pc2 : pc1w;
    float x = src[b * 3 * NQ + i];
    float y = src[b * 3 * NQ + NQ + i];
    float z = src[b * 3 * NQ + 2 * NQ + i];
    int cx, cy, cz; cell_coords(x, y, z, cx, cy, cz);
    int c = (cz * G + cy) * G + cx;
    atomicAdd((isq ? g_cnt_q : g_cnt_r) + b * NC + c, 1);
}

// 3) exclusive scan per (array,batch): 8 blocks x 1024 threads, 32 cells/thread
__global__ __launch_bounds__(1024) void k_scan() {
    __shared__ int ssum[1024];
    int arr = blockIdx.x >> 2;              // 0 = ref, 1 = query
    int b   = blockIdx.x & 3;
    int* cnt   = (arr ? g_cnt_q : g_cnt_r) + b * NC;
    int* start = (arr ? g_start_q : g_start_r) + b * (NC + 1);
    int* cur   = (arr ? g_cur_q : g_cur_r) + b * NC;
    int tid = threadIdx.x;
    int base = tid * 32;
    int sum = 0;
#pragma unroll
    for (int k = 0; k < 32; k++) sum += cnt[base + k];
    ssum[tid] = sum;
    __syncthreads();
    for (int off = 1; off < 1024; off <<= 1) {
        int v = (tid >= off) ? ssum[tid - off] : 0;
        __syncthreads();
        if (tid >= off) ssum[tid] += v;
        __syncthreads();
    }
    int run = ssum[tid] - sum;              // exclusive
#pragma unroll
    for (int k = 0; k < 32; k++) {
        int v = cnt[base + k];
        start[base + k] = run;
        cur[base + k] = run;
        run += v;
    }
    if (tid == 1023) start[NC] = run;
}

// 4) scatter into cell-sorted arrays
__global__ void k_scatter(const float* __restrict__ pc2,
                          const float* __restrict__ pc1w) {
    int t = blockIdx.x * blockDim.x + threadIdx.x;
    if (t >= 2 * BQ * NQ) return;
    int isq = t >= BQ * NQ;
    int p = isq ? t - BQ * NQ : t;
    int b = p / NQ, i = p - b * NQ;
    const float* src = isq ? pc2 : pc1w;
    float x = src[b * 3 * NQ + i];
    float y = src[b * 3 * NQ + NQ + i];
    float z = src[b * 3 * NQ + 2 * NQ + i];
    int cx, cy, cz; cell_coords(x, y, z, cx, cy, cz);
    int c = (cz * G + cy) * G + cx;
    int pos = atomicAdd((isq ? g_cur_q : g_cur_r) + b * NC + c, 1);
    int o = b * NQ + pos;
    if (isq) { g_qx[o] = x; g_qy[o] = y; g_qz[o] = z; g_qid[o] = i; }
    else     { g_rx[o] = x; g_ry[o] = y; g_rz[o] = z; }
}

// 5) exact 1-NN via expanding Chebyshev rings. Queries are cell-sorted ->
// warp-coherent. Consecutive x-cells have contiguous candidate ranges.
__global__ __launch_bounds__(256) void k_nn() {
    int t = blockIdx.x * blockDim.x + threadIdx.x;   // 128*256 == BQ*NQ
    int b = t >> 13;
    float x = g_qx[t], y = g_qy[t], z = g_qz[t];
    int qid = g_qid[t];
    int cx, cy, cz; cell_coords(x, y, z, cx, cy, cz);
    const int*   start = g_start_r + b * (NC + 1);
    const float* rx = g_rx + b * NQ;
    const float* ry = g_ry + b * NQ;
    const float* rz = g_rz + b * NQ;

    float best = 3.0e38f;
    for (int r = 0; r < G; r++) {
        int zlo = max(cz - r, 0), zhi = min(cz + r, G - 1);
        int ylo = max(cy - r, 0), yhi = min(cy + r, G - 1);
        int xlo = max(cx - r, 0), xhi = min(cx + r, G - 1);
        for (int zz = zlo; zz <= zhi; zz++) {
            int ze = (zz - cz == r) | (cz - zz == r);
            for (int yy = ylo; yy <= yhi; yy++) {
                int rowbase = (zz * G + yy) * G;
                int edge = ze | (yy - cy == r) | (cy - yy == r);
                int c0, c1;
                if (edge) { c0 = rowbase + xlo; c1 = rowbase + xhi; }
                else {
                    // interior row: only x = cx-r and cx+r (r>=1 here)
                    if (cx - r >= 0) {
                        int c = rowbase + cx - r;
                        for (int j = start[c]; j < start[c + 1]; j++) {
                            float dx = rx[j] - x, dy = ry[j] - y, dz = rz[j] - z;
                            best = fminf(best, fmaf(dx, dx, fmaf(dy, dy, dz * dz)));
                        }
                    }
                    if (cx + r <= G - 1) {
                        int c = rowbase + cx + r;
                        for (int j = start[c]; j < start[c + 1]; j++) {
                            float dx = rx[j] - x, dy = ry[j] - y, dz = rz[j] - z;
                            best = fminf(best, fmaf(dx, dx, fmaf(dy, dy, dz * dz)));
                        }
                    }
                    continue;
                }
                for (int j = start[c0]; j < start[c1 + 1]; j++) {
                    float dx = rx[j] - x, dy = ry[j] - y, dz = rz[j] - z;
                    best = fminf(best, fmaf(dx, dx, fmaf(dy, dy, dz * dz)));
                }
            }
        }
        float bound = (float)r * CELL;       // rings > r are >= r*CELL away
        if (best <= bound * bound) break;
    }
    g_nn[b * NQ + qid] = fmaxf(best, 0.0f);  // deterministic placement
}

// 6) fixed-order reduction: 128 blocks x 256, one value per thread
__global__ __launch_bounds__(256) void k_red() {
    __shared__ float red[256];
    int tid = threadIdx.x;
    red[tid] = g_nn[blockIdx.x * 256 + tid];
    __syncthreads();
#pragma unroll
    for (int st = 128; st > 0; st >>= 1) {
        if (tid < st) red[tid] += red[tid + st];
        __syncthreads();
    }
    if (tid == 0) g_part[blockIdx.x] = red[0];
}

// 7) final: loss = 2 * mean_b(sum_n nn) = (2/BQ) * total
__global__ __launch_bounds__(128) void k_final(float* __restrict__ out) {
    __shared__ float red[128];
    int tid = threadIdx.x;
    red[tid] = g_part[tid];
    __syncthreads();
#pragma unroll
    for (int st = 64; st > 0; st >>= 1) {
        if (tid < st) red[tid] += red[tid + st];
        __syncthreads();
    }
    if (tid == 0) out[0] = red[0] * (2.0f / BQ);
}

extern "C" void kernel_launch(void* const* d_in, const int* in_sizes, int n_in,
                              void* d_out, int out_size) {
    const float* pc2  = (const float*)d_in[0];   // queries
    const float* pc1w = (const float*)d_in[1];   // refs
    float* out = (float*)d_out;

    k_zero<<<(BQ * NC + 255) / 256, 256>>>();
    k_count<<<(2 * BQ * NQ + 255) / 256, 256>>>(pc2, pc1w);
    k_scan<<<8, 1024>>>();
    k_scatter<<<(2 * BQ * NQ + 255) / 256, 256>>>(pc2, pc1w);
    k_nn<<<128, 256>>>();
    k_red<<<128, 256>>>();
    k_final<<<1, 128>>>(out);
}

// round 12
// speedup vs baseline: 2.0581x; 2.0581x over previous
#include <cuda_runtime.h>

#define BQ    4
#define NQ    8192
#define G     32
#define NC    (G * G * G)          // 32768 cells per batch
#define GRID_MIN (-3.0f)
#define CELL     (6.0f / G)        // 0.1875
#define INV_CELL (G / 6.0f)

// ---- scratch (__device__ globals; no allocation) ----
__device__ int   g_cnt[BQ * NC];
__device__ int   g_start[BQ * (NC + 1)];
__device__ int   g_cur[BQ * NC];
__device__ float g_rx[BQ * NQ], g_ry[BQ * NQ], g_rz[BQ * NQ];  // cell-sorted refs
__device__ float g_nn[BQ * NQ];                                 // nn sq dist per query
__device__ float g_part[128];

__device__ __forceinline__ int clampi(int v, int lo, int hi) {
    return v < lo ? lo : (v > hi ? hi : v);
}
__device__ __forceinline__ void cell_coords(float x, float y, float z,
                                            int& cx, int& cy, int& cz) {
    cx = clampi((int)floorf((x - GRID_MIN) * INV_CELL), 0, G - 1);
    cy = clampi((int)floorf((y - GRID_MIN) * INV_CELL), 0, G - 1);
    cz = clampi((int)floorf((z - GRID_MIN) * INV_CELL), 0, G - 1);
}

// 1) zero ref cell counts
__global__ void k_zero() {
    int i = blockIdx.x * blockDim.x + threadIdx.x;
    if (i < BQ * NC) g_cnt[i] = 0;
}

// 2) count refs per cell
__global__ void k_count(const float* __restrict__ pc1w) {
    int t = blockIdx.x * blockDim.x + threadIdx.x;
    if (t >= BQ * NQ) return;
    int b = t >> 13, i = t & (NQ - 1);
    float x = pc1w[b * 3 * NQ + i];
    float y = pc1w[b * 3 * NQ + NQ + i];
    float z = pc1w[b * 3 * NQ + 2 * NQ + i];
    int cx, cy, cz; cell_coords(x, y, z, cx, cy, cz);
    atomicAdd(&g_cnt[b * NC + (cz * G + cy) * G + cx], 1);
}

// 3) exclusive scan per batch: 4 blocks x 1024 threads, 32 cells/thread
__global__ __launch_bounds__(1024) void k_scan() {
    __shared__ int ssum[1024];
    int b = blockIdx.x;
    int* cnt   = g_cnt + b * NC;
    int* start = g_start + b * (NC + 1);
    int* cur   = g_cur + b * NC;
    int tid = threadIdx.x;
    int base = tid * 32;
    int sum = 0;
#pragma unroll
    for (int k = 0; k < 32; k++) sum += cnt[base + k];
    ssum[tid] = sum;
    __syncthreads();
    for (int off = 1; off < 1024; off <<= 1) {
        int v = (tid >= off) ? ssum[tid - off] : 0;
        __syncthreads();
        if (tid >= off) ssum[tid] += v;
        __syncthreads();
    }
    int run = ssum[tid] - sum;              // exclusive
#pragma unroll
    for (int k = 0; k < 32; k++) {
        int v = cnt[base + k];
        start[base + k] = run;
        cur[base + k] = run;
        run += v;
    }
    if (tid == 1023) start[NC] = run;
}

// 4) scatter refs into cell-sorted SoA
__global__ void k_scatter(const float* __restrict__ pc1w) {
    int t = blockIdx.x * blockDim.x + threadIdx.x;
    if (t >= BQ * NQ) return;
    int b = t >> 13, i = t & (NQ - 1);
    float x = pc1w[b * 3 * NQ + i];
    float y = pc1w[b * 3 * NQ + NQ + i];
    float z = pc1w[b * 3 * NQ + 2 * NQ + i];
    int cx, cy, cz; cell_coords(x, y, z, cx, cy, cz);
    int pos = atomicAdd(&g_cur[b * NC + (cz * G + cy) * G + cx], 1);
    int o = b * NQ + pos;
    g_rx[o] = x; g_ry[o] = y; g_rz[o] = z;
}

__device__ __forceinline__ float scan_pts(const float* __restrict__ rx,
                                          const float* __restrict__ ry,
                                          const float* __restrict__ rz,
                                          int j0, int j1,
                                          float x, float y, float z, float best) {
    for (int j = j0; j < j1; j++) {
        float dx = rx[j] - x, dy = ry[j] - y, dz = rz[j] - z;
        best = fminf(best, fmaf(dx, dx, fmaf(dy, dy, dz * dz)));
    }
    return best;
}

// 5) exact 1-NN, ONE WARP PER QUERY.
// Initial pass: 27-cell neighborhood, cell-per-lane (massive warp-level MLP).
// Fallback shells r>=2: row-per-lane, contiguous x-ranges.
__global__ __launch_bounds__(256) void k_nn(const float* __restrict__ pc2) {
    int warp = (blockIdx.x * blockDim.x + threadIdx.x) >> 5;   // 0 .. BQ*NQ-1
    int lane = threadIdx.x & 31;
    int b = warp >> 13, qi = warp & (NQ - 1);

    float x = pc2[b * 3 * NQ + qi];
    float y = pc2[b * 3 * NQ + NQ + qi];
    float z = pc2[b * 3 * NQ + 2 * NQ + qi];
    int cx, cy, cz; cell_coords(x, y, z, cx, cy, cz);

    const int*   start = g_start + b * (NC + 1);
    const float* rx = g_rx + b * NQ;
    const float* ry = g_ry + b * NQ;
    const float* rz = g_rz + b * NQ;

    float best = 3.0e38f;

    // ---- pass 1: cube r<=1, one cell per lane (27 lanes active) ----
    if (lane < 27) {
        int dz = lane / 9 - 1, dy = (lane / 3) % 3 - 1, dx = lane % 3 - 1;
        int zz = cz + dz, yy = cy + dy, xx = cx + dx;
        if (zz >= 0 && zz < G && yy >= 0 && yy < G && xx >= 0 && xx < G) {
            int c = (zz * G + yy) * G + xx;
            best = scan_pts(rx, ry, rz, start[c], start[c + 1], x, y, z, best);
        }
    }
#pragma unroll
    for (int o = 16; o > 0; o >>= 1)
        best = fminf(best, __shfl_xor_sync(0xFFFFFFFFu, best, o));

    if (best > CELL * CELL) {
        // ---- fallback shells: row-per-lane ----
        for (int r = 2; r < G; r++) {
            int side = 2 * r + 1, nrows = side * side;
            float lb = 3.0e38f;
            for (int w = lane; w < nrows; w += 32) {
                int dz = w / side - r, dy = w % side - r;
                int zz = cz + dz, yy = cy + dy;
                if (zz < 0 || zz >= G || yy < 0 || yy >= G) continue;
                int rowbase = (zz * G + yy) * G;
                if (dz == -r || dz == r || dy == -r || dy == r) {
                    int x0 = max(cx - r, 0), x1 = min(cx + r, G - 1);
                    lb = scan_pts(rx, ry, rz, start[rowbase + x0],
                                  start[rowbase + x1 + 1], x, y, z, lb);
                } else {
                    if (cx - r >= 0) {
                        int c = rowbase + cx - r;
                        lb = scan_pts(rx, ry, rz, start[c], start[c + 1], x, y, z, lb);
                    }
                    if (cx + r < G) {
                        int c = rowbase + cx + r;
                        lb = scan_pts(rx, ry, rz, start[c], start[c + 1], x, y, z, lb);
                    }
                }
            }
            best = fminf(best, lb);
#pragma unroll
            for (int o = 16; o > 0; o >>= 1)
                best = fminf(best, __shfl_xor_sync(0xFFFFFFFFu, best, o));
            float bound = (float)r * CELL;   // remaining points are >= r*CELL away
            if (best <= bound * bound) break;
            if (cx - r <= 0 && cx + r >= G - 1 && cy - r <= 0 && cy + r >= G - 1 &&
                cz - r <= 0 && cz + r >= G - 1) break;   // everything scanned
        }
    }

    if (lane == 0) g_nn[b * NQ + qi] = best;   // >= 0 by construction
}

// 6) fixed-order reduction: 128 blocks x 256, one value per thread
__global__ __launch_bounds__(256) void k_red() {
    __shared__ float red[256];
    int tid = threadIdx.x;
    red[tid] = g_nn[blockIdx.x * 256 + tid];
    __syncthreads();
#pragma unroll
    for (int st = 128; st > 0; st >>= 1) {
        if (tid < st) red[tid] += red[tid + st];
        __syncthreads();
    }
    if (tid == 0) g_part[blockIdx.x] = red[0];
}

// 7) final: loss = 2 * mean_b(sum_n nn) = (2/BQ) * total
__global__ __launch_bounds__(128) void k_final(float* __restrict__ out) {
    __shared__ float red[128];
    int tid = threadIdx.x;
    red[tid] = g_part[tid];
    __syncthreads();
#pragma unroll
    for (int st = 64; st > 0; st >>= 1) {
        if (tid < st) red[tid] += red[tid + st];
        __syncthreads();
    }
    if (tid == 0) out[0] = red[0] * (2.0f / BQ);
}

extern "C" void kernel_launch(void* const* d_in, const int* in_sizes, int n_in,
                              void* d_out, int out_size) {
    const float* pc2  = (const float*)d_in[0];   // queries
    const float* pc1w = (const float*)d_in[1];   // refs
    float* out = (float*)d_out;

    k_zero<<<(BQ * NC + 255) / 256, 256>>>();
    k_count<<<(BQ * NQ + 255) / 256, 256>>>(pc1w);
    k_scan<<<BQ, 1024>>>();
    k_scatter<<<(BQ * NQ + 255) / 256, 256>>>(pc1w);
    k_nn<<<(BQ * NQ * 32) / 256, 256>>>(pc2);
    k_red<<<128, 256>>>();
    k_final<<<1, 128>>>(out);
}

// round 15
// speedup vs baseline: 2.0780x; 1.0096x over previous
#include <cuda_runtime.h>

#define BQ    4
#define NQ    8192
#define G     32
#define NC    (G * G * G)          // 32768 cells per batch
#define GRID_MIN (-3.0f)
#define CELL     (6.0f / G)        // 0.1875
#define INV_CELL (G / 6.0f)
#define FULLM 0xFFFFFFFFu

// ---- scratch (__device__ globals; no allocation) ----
__device__ int    g_cnt[BQ * NC];
__device__ int    g_start[BQ * (NC + 1)];
__device__ int    g_cur[BQ * NC];
__device__ float4 g_ref[BQ * NQ];    // cell-sorted refs (x,y,z,0)
__device__ float  g_nn[BQ * NQ];     // nn sq dist per query (original index)
__device__ float  g_part[128];

__device__ __forceinline__ int clampi(int v, int lo, int hi) {
    return v < lo ? lo : (v > hi ? hi : v);
}
__device__ __forceinline__ void cell_coords(float x, float y, float z,
                                            int& cx, int& cy, int& cz) {
    cx = clampi((int)floorf((x - GRID_MIN) * INV_CELL), 0, G - 1);
    cy = clampi((int)floorf((y - GRID_MIN) * INV_CELL), 0, G - 1);
    cz = clampi((int)floorf((z - GRID_MIN) * INV_CELL), 0, G - 1);
}

// 1) zero ref cell counts
__global__ void k_zero() {
    int i = blockIdx.x * blockDim.x + threadIdx.x;
    if (i < BQ * NC) g_cnt[i] = 0;
}

// 2) count refs per cell
__global__ void k_count(const float* __restrict__ pc1w) {
    int t = blockIdx.x * blockDim.x + threadIdx.x;
    if (t >= BQ * NQ) return;
    int b = t >> 13, i = t & (NQ - 1);
    float x = pc1w[b * 3 * NQ + i];
    float y = pc1w[b * 3 * NQ + NQ + i];
    float z = pc1w[b * 3 * NQ + 2 * NQ + i];
    int cx, cy, cz; cell_coords(x, y, z, cx, cy, cz);
    atomicAdd(&g_cnt[b * NC + (cz * G + cy) * G + cx], 1);
}

// 3) exclusive scan per batch: 4 blocks x 1024 threads, 32 cells/thread
__global__ __launch_bounds__(1024) void k_scan() {
    __shared__ int ssum[1024];
    int b = blockIdx.x;
    int* cnt   = g_cnt + b * NC;
    int* start = g_start + b * (NC + 1);
    int* cur   = g_cur + b * NC;
    int tid = threadIdx.x;
    int base = tid * 32;
    int sum = 0;
#pragma unroll
    for (int k = 0; k < 32; k++) sum += cnt[base + k];
    ssum[tid] = sum;
    __syncthreads();
    for (int off = 1; off < 1024; off <<= 1) {
        int v = (tid >= off) ? ssum[tid - off] : 0;
        __syncthreads();
        if (tid >= off) ssum[tid] += v;
        __syncthreads();
    }
    int run = ssum[tid] - sum;              // exclusive
#pragma unroll
    for (int k = 0; k < 32; k++) {
        int v = cnt[base + k];
        start[base + k] = run;
        cur[base + k] = run;
        run += v;
    }
    if (tid == 1023) start[NC] = run;
}

// 4) scatter refs into cell-sorted float4 array
__global__ void k_scatter(const float* __restrict__ pc1w) {
    int t = blockIdx.x * blockDim.x + threadIdx.x;
    if (t >= BQ * NQ) return;
    int b = t >> 13, i = t & (NQ - 1);
    float x = pc1w[b * 3 * NQ + i];
    float y = pc1w[b * 3 * NQ + NQ + i];
    float z = pc1w[b * 3 * NQ + 2 * NQ + i];
    int cx, cy, cz; cell_coords(x, y, z, cx, cy, cz);
    int pos = atomicAdd(&g_cur[b * NC + (cz * G + cy) * G + cx], 1);
    g_ref[b * NQ + pos] = make_float4(x, y, z, 0.0f);
}

// 5) exact 1-NN, one warp per query, LANE-PER-CANDIDATE with coalesced
// float4 loads. The r<=1 neighborhood = 9 contiguous row ranges (refs are
// cell-sorted); warp builds a candidate list via shfl prefix scan, then all
// 32 lanes stream candidates together.
__global__ __launch_bounds__(256) void k_nn(const float* __restrict__ pc2) {
    int warp = (blockIdx.x * blockDim.x + threadIdx.x) >> 5;   // 0 .. BQ*NQ-1
    int lane = threadIdx.x & 31;
    int b = warp >> 13, qi = warp & (NQ - 1);

    float x = pc2[b * 3 * NQ + qi];
    float y = pc2[b * 3 * NQ + NQ + qi];
    float z = pc2[b * 3 * NQ + 2 * NQ + qi];
    int cx, cy, cz; cell_coords(x, y, z, cx, cy, cz);

    const int*    start = g_start + b * (NC + 1);
    const float4* ref   = g_ref + b * NQ;

    // --- 9 neighborhood rows: lane r (r<9) owns row (dz,dy) ---
    int my_s0 = 0, my_cnt = 0;
    if (lane < 9) {
        int dz = lane / 3 - 1, dy = lane % 3 - 1;
        int zz = cz + dz, yy = cy + dy;
        if (zz >= 0 && zz < G && yy >= 0 && yy < G) {
            int rowbase = (zz * G + yy) * G;
            int x0 = max(cx - 1, 0), x1 = min(cx + 1, G - 1);
            my_s0 = start[rowbase + x0];
            my_cnt = start[rowbase + x1 + 1] - my_s0;
        }
    }
    // inclusive shfl scan over lanes 0..8 -> exclusive prefix
    int incl = my_cnt;
#pragma unroll
    for (int o = 1; o < 16; o <<= 1) {
        int v = __shfl_up_sync(FULLM, incl, o);
        if (lane >= o) incl += v;
    }
    int my_p = incl - my_cnt;                       // exclusive prefix
    int total = __shfl_sync(FULLM, incl, 8);

    // broadcast row tables into per-lane register arrays (ALU-only lookup later)
    int pk[9], ck[9], sk[9];
#pragma unroll
    for (int k = 0; k < 9; k++) {
        pk[k] = __shfl_sync(FULLM, my_p, k);
        ck[k] = __shfl_sync(FULLM, my_cnt, k);
        sk[k] = __shfl_sync(FULLM, my_s0, k);
    }

    float best = 3.0e38f;
    for (int base = 0; base < total; base += 32) {
        int i = base + lane;
        if (i < total) {
            int addr = 0;
#pragma unroll
            for (int k = 0; k < 9; k++)
                if (i >= pk[k] && i < pk[k] + ck[k]) addr = sk[k] + (i - pk[k]);
            float4 rp = ref[addr];
            float dx = rp.x - x, dy = rp.y - y, dz = rp.z - z;
            best = fminf(best, fmaf(dx, dx, fmaf(dy, dy, dz * dz)));
        }
    }
#pragma unroll
    for (int o = 16; o > 0; o >>= 1)
        best = fminf(best, __shfl_xor_sync(FULLM, best, o));

    if (best > CELL * CELL) {
        // --- fallback shells r>=2: row-per-lane, float4 candidates (rare) ---
        for (int r = 2; r < G; r++) {
            int side = 2 * r + 1, nrows = side * side;
            float lb = 3.0e38f;
            for (int w = lane; w < nrows; w += 32) {
                int dz = w / side - r, dy = w % side - r;
                int zz = cz + dz, yy = cy + dy;
                if (zz < 0 || zz >= G || yy < 0 || yy >= G) continue;
                int rowbase = (zz * G + yy) * G;
                int j0, j1;
                if (dz == -r || dz == r || dy == -r || dy == r) {
                    int x0 = max(cx - r, 0), x1 = min(cx + r, G - 1);
                    j0 = start[rowbase + x0]; j1 = start[rowbase + x1 + 1];
                } else {
                    // interior row: only x = cx-r and cx+r; do left here
                    if (cx - r >= 0) {
                        int c = rowbase + cx - r;
                        for (int j = start[c]; j < start[c + 1]; j++) {
                            float4 rp = ref[j];
                            float dx2 = rp.x - x, dy2 = rp.y - y, dz2 = rp.z - z;
                            lb = fminf(lb, fmaf(dx2, dx2, fmaf(dy2, dy2, dz2 * dz2)));
                        }
                    }
                    if (cx + r >= G) continue;
                    int c = rowbase + cx + r;
                    j0 = start[c]; j1 = start[c + 1];
                }
                for (int j = j0; j < j1; j++) {
                    float4 rp = ref[j];
                    float dx2 = rp.x - x, dy2 = rp.y - y, dz2 = rp.z - z;
                    lb = fminf(lb, fmaf(dx2, dx2, fmaf(dy2, dy2, dz2 * dz2)));
                }
            }
            best = fminf(best, lb);
#pragma unroll
            for (int o = 16; o > 0; o >>= 1)
                best = fminf(best, __shfl_xor_sync(FULLM, best, o));
            float bound = (float)r * CELL;   // remaining points are >= r*CELL away
            if (best <= bound * bound) break;
            if (cx - r <= 0 && cx + r >= G - 1 && cy - r <= 0 && cy + r >= G - 1 &&
                cz - r <= 0 && cz + r >= G - 1) break;   // everything scanned
        }
    }

    if (lane == 0) g_nn[b * NQ + qi] = best;   // >= 0 by construction
}

// 6) fixed-order reduction: 128 blocks x 256, one value per thread
__global__ __launch_bounds__(256) void k_red() {
    __shared__ float red[256];
    int tid = threadIdx.x;
    red[tid] = g_nn[blockIdx.x * 256 + tid];
    __syncthreads();
#pragma unroll
    for (int st = 128; st > 0; st >>= 1) {
        if (tid < st) red[tid] += red[tid + st];
        __syncthreads();
    }
    if (tid == 0) g_part[blockIdx.x] = red[0];
}

// 7) final: loss = 2 * mean_b(sum_n nn) = (2/BQ) * total
__global__ __launch_bounds__(128) void k_final(float* __restrict__ out) {
    __shared__ float red[128];
    int tid = threadIdx.x;
    red[tid] = g_part[tid];
    __syncthreads();
#pragma unroll
    for (int st = 64; st > 0; st >>= 1) {
        if (tid < st) red[tid] += red[tid + st];
        __syncthreads();
    }
    if (tid == 0) out[0] = red[0] * (2.0f / BQ);
}

extern "C" void kernel_launch(void* const* d_in, const int* in_sizes, int n_in,
                              void* d_out, int out_size) {
    const float* pc2  = (const float*)d_in[0];   // queries
    const float* pc1w = (const float*)d_in[1];   // refs
    float* out = (float*)d_out;

    k_zero<<<(BQ * NC + 255) / 256, 256>>>();
    k_count<<<(BQ * NQ + 255) / 256, 256>>>(pc1w);
    k_scan<<<BQ, 1024>>>();
    k_scatter<<<(BQ * NQ + 255) / 256, 256>>>(pc1w);
    k_nn<<<(BQ * NQ * 32) / 256, 256>>>(pc2);
    k_red<<<128, 256>>>();
    k_final<<<1, 128>>>(out);
}